// round 8
// baseline (speedup 1.0000x reference)
#include <cuda_runtime.h>
#include <cuda_bf16.h>
#include <math.h>
#include <stdint.h>

#define NN 20000
#define EE 320000
#define IND 128
#define HH 8
#define CC 128
#define HCD 1024
#define GG 64
#define NEG_SLOPE 0.2f

// ---------------- scratch (static device globals; no allocation) ----------------
__device__ __nv_bfloat16 g_xl_bf[(size_t)NN * HCD];   // x@Wl+bl (41 MB)
__device__ __nv_bfloat16 g_xr_bf[(size_t)NN * HCD];   // x@Wr+br (41 MB)
__device__ float g_out[(size_t)NN * HCD];             // residual -> attn output (82 MB)
__device__ float g_h[(size_t)NN * CC];                // ELU(Linear) (10 MB)
__device__ int   g_deg[NN];
__device__ int   g_rowptr[NN + 1];
__device__ int   g_cursor[NN];
__device__ int   g_adj[EE];
__device__ float g_pooled[GG * CC];

// ---------------- CSR build ----------------
__global__ void init_k() {
    int idx = blockIdx.x * 256 + threadIdx.x;
    if (idx < NN) g_deg[idx] = 0;
}

__global__ void deg_k(const int* __restrict__ ei) {
    int e = blockIdx.x * 256 + threadIdx.x;
    if (e < EE) atomicAdd(&g_deg[ei[EE + e]], 1);
}

__global__ void scan_k() {
    __shared__ int warp_sums[32];
    int tid = threadIdx.x;
    int start = tid * 20;
    int v[20];
    int tot = 0;
#pragma unroll
    for (int j = 0; j < 20; j++) {
        int idx = start + j;
        int d = (idx < NN) ? g_deg[idx] : 0;
        v[j] = tot;
        tot += d;
    }
    int lane = tid & 31, wid = tid >> 5;
    int x = tot;
#pragma unroll
    for (int off = 1; off < 32; off <<= 1) {
        int t = __shfl_up_sync(0xffffffffu, x, off);
        if (lane >= off) x += t;
    }
    if (lane == 31) warp_sums[wid] = x;
    __syncthreads();
    if (wid == 0) {
        int w = warp_sums[lane];
#pragma unroll
        for (int off = 1; off < 32; off <<= 1) {
            int t = __shfl_up_sync(0xffffffffu, w, off);
            if (lane >= off) w += t;
        }
        warp_sums[lane] = w;
    }
    __syncthreads();
    int base = x - tot + (wid > 0 ? warp_sums[wid - 1] : 0);
#pragma unroll
    for (int j = 0; j < 20; j++) {
        int idx = start + j;
        if (idx <= NN) {
            int ex = base + v[j];
            g_rowptr[idx] = ex;
            if (idx < NN) g_cursor[idx] = ex;
        }
    }
}

__global__ void adj_k(const int* __restrict__ ei) {
    int e = blockIdx.x * 256 + threadIdx.x;
    if (e < EE) {
        int pos = atomicAdd(&g_cursor[ei[EE + e]], 1);
        g_adj[pos] = e;
    }
}

// ---------------- tf32 tensor-core GEMM, 2-stage pipelined ----------------
// mode 0: bf16 -> g_xl_bf ; 1: bf16 -> g_xr_bf ; 2: f32 -> g_out ; 3: ELU f32 -> g_h
__device__ __forceinline__ uint32_t f2tf32(float v) {
    uint32_t o;
    asm("cvt.rna.tf32.f32 %0, %1;" : "=r"(o) : "f"(v));
    return o;
}

__device__ __forceinline__ void mma_tf32(float c[4], uint32_t a0, uint32_t a1,
                                         uint32_t a2, uint32_t a3, uint32_t b0, uint32_t b1) {
    asm volatile(
        "mma.sync.aligned.m16n8k8.row.col.f32.tf32.tf32.f32 "
        "{%0,%1,%2,%3},{%4,%5,%6,%7},{%8,%9},{%0,%1,%2,%3};"
        : "+f"(c[0]), "+f"(c[1]), "+f"(c[2]), "+f"(c[3])
        : "r"(a0), "r"(a1), "r"(a2), "r"(a3), "r"(b0), "r"(b1));
}

#define SA_STRIDE 36
#define SB_STRIDE 136
#define SA_STAGE (128 * SA_STRIDE)
#define SB_STAGE (32 * SB_STRIDE)
#define GEMM_SMEM_BYTES ((2 * SA_STAGE + 2 * SB_STAGE) * 4)

__global__ __launch_bounds__(256) void gemm_tc_k(
    const float* __restrict__ Xf, int x_is_gout,
    const float* __restrict__ W, const float* __restrict__ bias,
    int M, int K, int N, int mode) {
    extern __shared__ uint32_t smem[];
    uint32_t* s_a = smem;                       // [2][128][36]
    uint32_t* s_b = smem + 2 * SA_STAGE;        // [2][32][136]

    const float* X = x_is_gout ? g_out : Xf;
    int tid = threadIdx.x;
    int lane = tid & 31, warp = tid >> 5;
    int wm = warp & 3, wn = warp >> 2;
    int m0 = wm * 32, n0 = wn * 64;
    int mBase = blockIdx.y * 128, nBase = blockIdx.x * 128;

    float acc[2][8][4];
#pragma unroll
    for (int mt = 0; mt < 2; mt++)
#pragma unroll
        for (int nt = 0; nt < 8; nt++)
#pragma unroll
            for (int c = 0; c < 4; c++) acc[mt][nt][c] = 0.f;

    int aRowBase = tid >> 3, aK4 = tid & 7;   // A: rows aRowBase+32i, one float4 @ col aK4
    int bK = tid >> 3, bC = tid & 7;          // B: row bK, float4 cols bC+8i

    float4 aReg[4], bReg[4];

    // prologue: load chunk 0
#pragma unroll
    for (int i = 0; i < 4; i++) {
        int gr = mBase + aRowBase + i * 32;
        aReg[i] = (gr < M) ? *(const float4*)&X[(size_t)gr * K + aK4 * 4]
                           : make_float4(0.f, 0.f, 0.f, 0.f);
        bReg[i] = *(const float4*)&W[(size_t)bK * N + nBase + (bC + 8 * i) * 4];
    }

    int s = 0;
    for (int kb = 0; kb < K; kb += 32) {
        // store prefetched chunk -> smem[s] (with tf32 convert)
#pragma unroll
        for (int i = 0; i < 4; i++) {
            int m = aRowBase + i * 32;
            uint4 at = make_uint4(f2tf32(aReg[i].x), f2tf32(aReg[i].y),
                                  f2tf32(aReg[i].z), f2tf32(aReg[i].w));
            *(uint4*)&s_a[s * SA_STAGE + m * SA_STRIDE + aK4 * 4] = at;
            uint4 bt = make_uint4(f2tf32(bReg[i].x), f2tf32(bReg[i].y),
                                  f2tf32(bReg[i].z), f2tf32(bReg[i].w));
            *(uint4*)&s_b[s * SB_STAGE + bK * SB_STRIDE + (bC + 8 * i) * 4] = bt;
        }
        __syncthreads();

        // prefetch next chunk (overlaps with compute below)
        int kn = kb + 32;
        if (kn < K) {
#pragma unroll
            for (int i = 0; i < 4; i++) {
                int gr = mBase + aRowBase + i * 32;
                aReg[i] = (gr < M) ? *(const float4*)&X[(size_t)gr * K + kn + aK4 * 4]
                                   : make_float4(0.f, 0.f, 0.f, 0.f);
                bReg[i] = *(const float4*)&W[(size_t)(kn + bK) * N + nBase + (bC + 8 * i) * 4];
            }
        }

        // compute on smem[s]
        const uint32_t* pa = &s_a[s * SA_STAGE];
        const uint32_t* pb = &s_b[s * SB_STAGE];
#pragma unroll
        for (int kk = 0; kk < 4; kk++) {
            uint32_t a[2][4];
#pragma unroll
            for (int mt = 0; mt < 2; mt++) {
                int r = m0 + mt * 16 + (lane >> 2);
                int c = kk * 8 + (lane & 3);
                a[mt][0] = pa[r * SA_STRIDE + c];
                a[mt][1] = pa[(r + 8) * SA_STRIDE + c];
                a[mt][2] = pa[r * SA_STRIDE + c + 4];
                a[mt][3] = pa[(r + 8) * SA_STRIDE + c + 4];
            }
#pragma unroll
            for (int nt = 0; nt < 8; nt++) {
                int n = n0 + nt * 8 + (lane >> 2);
                uint32_t b0 = pb[(kk * 8 + (lane & 3)) * SB_STRIDE + n];
                uint32_t b1 = pb[(kk * 8 + (lane & 3) + 4) * SB_STRIDE + n];
                mma_tf32(acc[0][nt], a[0][0], a[0][1], a[0][2], a[0][3], b0, b1);
                mma_tf32(acc[1][nt], a[1][0], a[1][1], a[1][2], a[1][3], b0, b1);
            }
        }
        s ^= 1;
    }

    // epilogue
#pragma unroll
    for (int mt = 0; mt < 2; mt++) {
#pragma unroll
        for (int nt = 0; nt < 8; nt++) {
            int r0 = mBase + m0 + mt * 16 + (lane >> 2);
            int cb = nBase + n0 + nt * 8 + (lane & 3) * 2;
            float bb0 = bias[cb], bb1 = bias[cb + 1];
            float v0 = acc[mt][nt][0] + bb0;
            float v1 = acc[mt][nt][1] + bb1;
            float v2 = acc[mt][nt][2] + bb0;
            float v3 = acc[mt][nt][3] + bb1;
            if (mode == 3) {
                v0 = v0 > 0.f ? v0 : (__expf(v0) - 1.f);
                v1 = v1 > 0.f ? v1 : (__expf(v1) - 1.f);
                v2 = v2 > 0.f ? v2 : (__expf(v2) - 1.f);
                v3 = v3 > 0.f ? v3 : (__expf(v3) - 1.f);
                if (r0 < M) *(float2*)&g_h[(size_t)r0 * N + cb] = make_float2(v0, v1);
                if (r0 + 8 < M) *(float2*)&g_h[(size_t)(r0 + 8) * N + cb] = make_float2(v2, v3);
            } else if (mode == 2) {
                if (r0 < M) *(float2*)&g_out[(size_t)r0 * N + cb] = make_float2(v0, v1);
                if (r0 + 8 < M) *(float2*)&g_out[(size_t)(r0 + 8) * N + cb] = make_float2(v2, v3);
            } else {
                __nv_bfloat16* D = (mode == 0) ? g_xl_bf : g_xr_bf;
                if (r0 < M)
                    *(__nv_bfloat162*)&D[(size_t)r0 * N + cb] = __floats2bfloat162_rn(v0, v1);
                if (r0 + 8 < M)
                    *(__nv_bfloat162*)&D[(size_t)(r0 + 8) * N + cb] = __floats2bfloat162_rn(v2, v3);
            }
        }
    }
}

// ---------------- fused per-node GATv2 with smem-staged xl rows ----------------
#define CHKF 16
__global__ __launch_bounds__(256) void node_attn_k(const int* __restrict__ ei,
                                                   const float* __restrict__ att) {
    int i = blockIdx.x;
    int tid = threadIdx.x, lane = tid & 31, wid = tid >> 5;
    int beg = g_rowptr[i], end = g_rowptr[i + 1];

    __shared__ float s_att[HCD];                       // 4 KB
    __shared__ float s_xr[HCD];                        // 4 KB
    __shared__ __nv_bfloat16 s_xl[CHKF][HCD];          // 32 KB staged rows
    __shared__ float s_logit[CHKF][9];
    __shared__ float s_scale[HH];
    __shared__ float s_inv[HH];

#pragma unroll
    for (int q = 0; q < 4; q++) s_att[tid + q * 256] = att[tid + q * 256];
    if (tid < 128) {
        uint4 raw = ((const uint4*)&g_xr_bf[(size_t)i * HCD])[tid];
        const __nv_bfloat162* p = (const __nv_bfloat162*)&raw;
#pragma unroll
        for (int q = 0; q < 4; q++) {
            float2 f = __bfloat1622float2(p[q]);
            s_xr[tid * 8 + q * 2 + 0] = f.x;
            s_xr[tid * 8 + q * 2 + 1] = f.y;
        }
    }
    __syncthreads();

    float run_m = -3.4e38f, run_s = 0.f;
    float acc0 = 0.f, acc1 = 0.f, acc2 = 0.f, acc3 = 0.f;
    int h = tid >> 5;

    for (int cb = beg; cb < end; cb += CHKF) {
        int cnt = min(CHKF, end - cb);

        // phase 1: logits + stage xl rows into smem (warp per edge)
        for (int k = wid; k < cnt; k += 8) {
            int eid = g_adj[cb + k];
            int src = ei[eid];
            const uint4* A = (const uint4*)&g_xl_bf[(size_t)src * HCD];
            uint4* S = (uint4*)&s_xl[k][0];
#pragma unroll
            for (int it = 0; it < 4; it++) {
                int j = it * 32 + lane;
                uint4 av = A[j];
                S[j] = av;
                const __nv_bfloat162* ap = (const __nv_bfloat162*)&av;
                float v = 0.f;
#pragma unroll
                for (int q = 0; q < 4; q++) {
                    float2 fa = __bfloat1622float2(ap[q]);
                    float sx = fa.x + s_xr[j * 8 + q * 2];
                    float sy = fa.y + s_xr[j * 8 + q * 2 + 1];
                    sx = sx > 0.f ? sx : NEG_SLOPE * sx;
                    sy = sy > 0.f ? sy : NEG_SLOPE * sy;
                    v += sx * s_att[j * 8 + q * 2] + sy * s_att[j * 8 + q * 2 + 1];
                }
#pragma unroll
                for (int off = 8; off > 0; off >>= 1)
                    v += __shfl_down_sync(0xffffffffu, v, off, 16);
                if ((lane & 15) == 0) s_logit[k][it * 2 + (lane >> 4)] = v;
            }
        }
        __syncthreads();

        // phase 2: per-head streaming stats (warp wid = head wid)
        {
            float cm = -3.4e38f;
            for (int k = lane; k < cnt; k += 32) cm = fmaxf(cm, s_logit[k][wid]);
#pragma unroll
            for (int off = 16; off > 0; off >>= 1)
                cm = fmaxf(cm, __shfl_xor_sync(0xffffffffu, cm, off));
            float nm = fmaxf(run_m, cm);
            float csum = 0.f;
            for (int k = lane; k < cnt; k += 32) {
                float w = __expf(s_logit[k][wid] - nm);
                s_logit[k][wid] = w;
                csum += w;
            }
#pragma unroll
            for (int off = 16; off > 0; off >>= 1)
                csum += __shfl_xor_sync(0xffffffffu, csum, off);
            float scale = __expf(run_m - nm);
            run_s = run_s * scale + csum;
            run_m = nm;
            if (lane == 0) s_scale[wid] = scale;
        }
        __syncthreads();

        // phase 3: weighted aggregate from SMEM (no global re-gather)
        float sc = s_scale[h];
        acc0 *= sc; acc1 *= sc; acc2 *= sc; acc3 *= sc;
        for (int k = 0; k < cnt; k++) {
            float a = s_logit[k][h];
            uint2 raw = ((const uint2*)&s_xl[k][0])[tid];
            float2 p0 = __bfloat1622float2(*(const __nv_bfloat162*)&raw.x);
            float2 p1 = __bfloat1622float2(*(const __nv_bfloat162*)&raw.y);
            acc0 += a * p0.x;
            acc1 += a * p0.y;
            acc2 += a * p1.x;
            acc3 += a * p1.y;
        }
        __syncthreads();
    }

    if (lane == 0) s_inv[wid] = (run_s > 0.f) ? 1.f / run_s : 0.f;
    __syncthreads();
    float inv = s_inv[h];

    float4* orow = (float4*)&g_out[(size_t)i * HCD];
    float4 r = orow[tid];
    orow[tid] = make_float4(acc0 * inv + r.x, acc1 * inv + r.y,
                            acc2 * inv + r.z, acc3 * inv + r.w);
}

// ---------------- deterministic mean pool (batch sorted) ----------------
__global__ void pool_k(const int* __restrict__ batch) {
    int g = blockIdx.x;
    __shared__ int sb, se;
    __shared__ float red[256];
    if (threadIdx.x == 0) {
        int lo = 0, hi = NN;
        while (lo < hi) { int mid = (lo + hi) >> 1; if (batch[mid] < g) lo = mid + 1; else hi = mid; }
        sb = lo;
        lo = 0; hi = NN;
        while (lo < hi) { int mid = (lo + hi) >> 1; if (batch[mid] <= g) lo = mid + 1; else hi = mid; }
        se = lo;
    }
    __syncthreads();
    int beg = sb, end = se;
    int ch = threadIdx.x & 127, half = threadIdx.x >> 7;
    float acc = 0.f;
    for (int n = beg + half; n < end; n += 2) acc += g_h[(size_t)n * CC + ch];
    red[threadIdx.x] = acc;
    __syncthreads();
    if (half == 0) {
        float v = red[ch] + red[128 + ch];
        float c = (end > beg) ? (float)(end - beg) : 1.f;
        g_pooled[g * CC + ch] = v / c;
    }
}

// ---------------- MLP head ----------------
__global__ void head_k(const float* __restrict__ W1, const float* __restrict__ b1,
                       const float* __restrict__ W2, const float* __restrict__ b2,
                       const float* __restrict__ W3, const float* __restrict__ b3,
                       float* __restrict__ out) {
    __shared__ float sp[GG][CC];
    __shared__ float h1[GG][16];
    __shared__ float h2[GG][32];
    int tid = threadIdx.x;
    for (int idx = tid; idx < GG * CC; idx += 256) sp[idx >> 7][idx & 127] = g_pooled[idx];
    __syncthreads();
    for (int idx = tid; idx < GG * 16; idx += 256) {
        int g = idx / 16, o = idx % 16;
        float s = b1[o];
        for (int k = 0; k < CC; k++) s += sp[g][k] * W1[k * 16 + o];
        h1[g][o] = s > 0.f ? s : 0.f;
    }
    __syncthreads();
    for (int idx = tid; idx < GG * 32; idx += 256) {
        int g = idx / 32, o = idx % 32;
        float s = b2[o];
        for (int k = 0; k < 16; k++) s += h1[g][k] * W2[k * 32 + o];
        h2[g][o] = s > 0.f ? s : 0.f;
    }
    __syncthreads();
    for (int idx = tid; idx < GG * 5; idx += 256) {
        int g = idx / 5, o = idx % 5;
        float s = b3[o];
        for (int k = 0; k < 32; k++) s += h2[g][k] * W3[k * 5 + o];
        out[idx] = s;
    }
}

// ---------------- launch ----------------
extern "C" void kernel_launch(void* const* d_in, const int* in_sizes, int n_in,
                              void* d_out, int out_size) {
    const float* x = (const float*)d_in[0];
    const int* ei = (const int*)d_in[1];
    const int* batch = (const int*)d_in[2];
    const float* Wl = (const float*)d_in[3];
    const float* bl = (const float*)d_in[4];
    const float* Wr = (const float*)d_in[5];
    const float* br = (const float*)d_in[6];
    const float* att = (const float*)d_in[7];
    const float* Wres = (const float*)d_in[8];
    const float* bias_attn = (const float*)d_in[9];
    const float* W_lin = (const float*)d_in[10];
    const float* b_lin = (const float*)d_in[11];
    const float* W1 = (const float*)d_in[12];
    const float* b1 = (const float*)d_in[13];
    const float* W2 = (const float*)d_in[14];
    const float* b2 = (const float*)d_in[15];
    const float* W3 = (const float*)d_in[16];
    const float* b3 = (const float*)d_in[17];
    float* out = (float*)d_out;

    cudaFuncSetAttribute(gemm_tc_k, cudaFuncAttributeMaxDynamicSharedMemorySize,
                         GEMM_SMEM_BYTES);

    // CSR build
    init_k<<<(NN + 255) / 256, 256>>>();
    deg_k<<<(EE + 255) / 256, 256>>>(ei);
    scan_k<<<1, 1024>>>();
    adj_k<<<(EE + 255) / 256, 256>>>(ei);

    // dense transforms (tf32 tensor cores, pipelined)
    dim3 blk(256);
    dim3 g1(HCD / 128, (NN + 127) / 128);
    gemm_tc_k<<<g1, blk, GEMM_SMEM_BYTES>>>(x, 0, Wl, bl, NN, IND, HCD, 0);
    gemm_tc_k<<<g1, blk, GEMM_SMEM_BYTES>>>(x, 0, Wr, br, NN, IND, HCD, 1);
    gemm_tc_k<<<g1, blk, GEMM_SMEM_BYTES>>>(x, 0, Wres, bias_attn, NN, IND, HCD, 2);

    // fused GATv2 attention
    node_attn_k<<<NN, 256>>>(ei, att);

    // Linear + ELU (A = g_out fp32)
    dim3 g2(CC / 128, (NN + 127) / 128);
    gemm_tc_k<<<g2, blk, GEMM_SMEM_BYTES>>>(nullptr, 1, W_lin, b_lin, NN, HCD, CC, 3);

    // pool + head
    pool_k<<<GG, 256>>>(batch);
    head_k<<<1, 256>>>(W1, b1, W2, b2, W3, b3, out);
}